// round 3
// baseline (speedup 1.0000x reference)
#include <cuda_runtime.h>
#include <cuda_bf16.h>
#include <cstdint>

// Per-batch 21x21 cross-correlation, reflect padding 10.
// input: (16,3,768,768) f32   kernel: (16,21,21) f32   out: (16,3,768,768) f32
// Packed f32x2 FFMA version: pair over kernel-column j, lanes = even/odd j partial sums.

#define BB 16
#define CC 3
#define HH 768
#define WW 768
#define KK 21
#define PP 10

#define TH 32            // output rows per CTA (2 per thread, 16 ty groups)
#define TW 256           // output cols per CTA (16 per thread, 16 tx groups)
#define IH (TH + KK - 1) // 52 input rows in tile
#define SW 280           // smem row stride (floats): >= TW+40, mult of 4 (16B aligned)
#define KROW 24          // kernel smem row stride (zero padded)

#define SMEM_TILE_FLOATS (IH * SW)          // 14560
#define SMEM_KERN_FLOATS (KK * KROW)        // 504
#define SMEM_BYTES ((SMEM_TILE_FLOATS + SMEM_KERN_FLOATS) * 4)  // 60256

__device__ __forceinline__ int reflect_idx(int t) {
    if (t < 0) return -t;
    if (t >= HH) return 2 * HH - 2 - t;
    return t;
}

// 16B shared load -> two aligned 64b (f32x2) pairs
__device__ __forceinline__ void lds_v2u64(uint64_t& a, uint64_t& b, uint32_t addr) {
    asm volatile("ld.shared.v2.u64 {%0, %1}, [%2];"
                 : "=l"(a), "=l"(b) : "r"(addr));
}

// d.lo += a.lo*b.lo ; d.hi += a.hi*b.hi   (one SASS FFMA2)
__device__ __forceinline__ void ffma2(uint64_t& d, uint64_t a, uint64_t b) {
    asm("fma.rn.f32x2 %0, %1, %2, %0;" : "+l"(d) : "l"(a), "l"(b));
}

__device__ __forceinline__ float pair_sum(uint64_t p) {
    float lo, hi;
    asm("mov.b64 {%0, %1}, %2;" : "=f"(lo), "=f"(hi) : "l"(p));
    return lo + hi;
}

__global__ __launch_bounds__(256, 1)
void blur_kernel(const float* __restrict__ in,
                 const float* __restrict__ ker,
                 float* __restrict__ out)
{
    extern __shared__ float smem[];
    float* tile  = smem;                       // IH x SW
    float* skern = smem + SMEM_TILE_FLOATS;    // KK x KROW (zero padded)

    const int tid = threadIdx.x;
    const int bx = blockIdx.x;             // 0..2   (W tiles)
    const int by = blockIdx.y;             // 0..23  (H tiles)
    const int bz = blockIdx.z;             // 0..47  (b*3+c)
    const int b  = bz / CC;

    // ---- per-batch kernel into smem, stride 24, zero padded ----
    {
        const float* kp = ker + b * (KK * KK);
        for (int idx = tid; idx < KK * KROW; idx += 256) {
            int i = idx / KROW;
            int j = idx - i * KROW;
            skern[idx] = (j < KK) ? kp[i * KK + j] : 0.f;
        }
    }

    // ---- input halo tile, full SW width, reflect indexing ----
    {
        const int gh0 = by * TH - PP;
        const int gw0 = bx * TW - PP;
        const float* img = in + (long)bz * (HH * WW);
        for (int idx = tid; idx < IH * SW; idx += 256) {
            int r  = idx / SW;
            int cc = idx - r * SW;
            int gh = reflect_idx(gh0 + r);
            int gw = reflect_idx(gw0 + cc);
            tile[idx] = img[gh * WW + gw];
        }
    }
    __syncthreads();

    const int tx = tid & 15;     // 0..15 -> 16-wide column group
    const int ty = tid >> 4;     // 0..15 -> output row pair
    const int wc = tx * 16;      // local col of first output (64B aligned)
    const int rb = ty * 2;       // first output row of this thread

    const uint32_t tile_base  = (uint32_t)__cvta_generic_to_shared(tile);
    const uint32_t kern_base  = (uint32_t)__cvta_generic_to_shared(skern);
    const uint32_t row0_addr  = tile_base + (uint32_t)((rb * SW + wc) * 4);

    // accumulators: lanes = (sum over even j, sum over odd j)
    uint64_t pc0[16], pc1[16];
    #pragma unroll
    for (int c = 0; c < 16; ++c) { pc0[c] = 0ull; pc1[c] = 0ull; }

    uint64_t e[20];    // even-parity pairs (x[2k], x[2k+1]), 40 floats of window
    uint64_t xo[18];   // odd-parity pairs  (x[2k+1], x[2k+2])

    // load 40-float window row, build both parity views
    #define LOADROW(t) do {                                                   \
        uint32_t a_ = row0_addr + (uint32_t)((t) * SW * 4);                   \
        _Pragma("unroll")                                                     \
        for (int v = 0; v < 10; ++v)                                          \
            lds_v2u64(e[2*v], e[2*v+1], a_ + v * 16);                         \
        _Pragma("unroll")                                                     \
        for (int k = 0; k < 18; ++k)                                          \
            xo[k] = (e[k] >> 32) | (e[k+1] << 32);                            \
    } while (0)

    // pc[c] += sum over j-pairs of window x weight-row t (11 pairs, w21 = 0)
    #define ACC(PC, t) do {                                                   \
        uint64_t wp_[12];                                                     \
        uint32_t ka_ = kern_base + (uint32_t)((t) * KROW * 4);                \
        _Pragma("unroll")                                                     \
        for (int v = 0; v < 6; ++v)                                           \
            lds_v2u64(wp_[2*v], wp_[2*v+1], ka_ + v * 16);                    \
        _Pragma("unroll")                                                     \
        for (int jp = 0; jp < 11; ++jp) {                                     \
            _Pragma("unroll")                                                 \
            for (int c = 0; c < 16; ++c) {                                    \
                const int ix_ = jp + (c >> 1);                                \
                ffma2(PC[c], (c & 1) ? xo[ix_] : e[ix_], wp_[jp]);            \
            }                                                                 \
        }                                                                     \
    } while (0)

    // t = 0: only output row 0 (weight row 0)
    LOADROW(0);
    ACC(pc0, 0);

    // t = 1..20: row t -> pc0 with weight row t, pc1 with weight row t-1
    #pragma unroll 1
    for (int t = 1; t <= 20; ++t) {
        LOADROW(t);
        ACC(pc0, t);
        ACC(pc1, t - 1);
    }

    // t = 21: only output row 1 (weight row 20)
    LOADROW(21);
    ACC(pc1, 20);

    // ---- reduce lanes, write 2 x 16 outputs as float4 ----
    const int oh = by * TH + rb;
    const int ow = bx * TW + wc;
    float* op0 = out + (long)bz * (HH * WW) + (long)oh * WW + ow;
    float* op1 = op0 + WW;

    float r0[16], r1[16];
    #pragma unroll
    for (int c = 0; c < 16; ++c) { r0[c] = pair_sum(pc0[c]); r1[c] = pair_sum(pc1[c]); }

    #pragma unroll
    for (int v = 0; v < 4; ++v) {
        *reinterpret_cast<float4*>(op0 + 4 * v) =
            make_float4(r0[4*v], r0[4*v+1], r0[4*v+2], r0[4*v+3]);
        *reinterpret_cast<float4*>(op1 + 4 * v) =
            make_float4(r1[4*v], r1[4*v+1], r1[4*v+2], r1[4*v+3]);
    }

    #undef LOADROW
    #undef ACC
}

extern "C" void kernel_launch(void* const* d_in, const int* in_sizes, int n_in,
                              void* d_out, int out_size)
{
    const float* in  = (const float*)d_in[0];   // (16,3,768,768)
    const float* ker = (const float*)d_in[1];   // (16,21,21)
    float* out = (float*)d_out;

    cudaFuncSetAttribute(blur_kernel,
                         cudaFuncAttributeMaxDynamicSharedMemorySize, SMEM_BYTES);

    dim3 grid(WW / TW, HH / TH, BB * CC);       // (3, 24, 48)
    blur_kernel<<<grid, 256, SMEM_BYTES>>>(in, ker, out);
}

// round 4
// speedup vs baseline: 1.4225x; 1.4225x over previous
#include <cuda_runtime.h>
#include <cuda_bf16.h>
#include <cstdint>

// Per-batch 21x21 cross-correlation, reflect padding 10.
// input: (16,3,768,768) f32   kernel: (16,21,21) f32   out: (16,3,768,768) f32
// FFMA2 (fma.rn.f32x2) with lanes = two adjacent OUTPUT ROWS.
// Weight pairs (w[i][j], w[i-1][j]) precomputed in a smem table (no per-use packing).

#define BB 16
#define CC 3
#define HH 768
#define WW 768
#define KK 21
#define PP 10

#define TH 64            // output rows per CTA (4 per thread: 16 ty groups)
#define TW 128           // output cols per CTA (8 per thread: 16 tx groups)
#define IH (TH + KK - 1) // 84 input rows in tile
#define SW 152           // smem tile row stride (floats), 16B aligned
#define WPS 24           // weight-pair table row stride (pairs)

#define TILE_FLOATS (IH * SW)          // 12768
#define WP_PAIRS    (22 * WPS)         // 528
#define SMEM_BYTES  (TILE_FLOATS * 4 + WP_PAIRS * 8)   // 51072 + 4224 = 55296

__device__ __forceinline__ int reflect_idx(int t) {
    if (t < 0) return -t;
    if (t >= HH) return 2 * HH - 2 - t;
    return t;
}

// broadcast float into both lanes of a 64b pair (held as double reg pair)
__device__ __forceinline__ double bcast(float x) {
    double r;
    asm("mov.b64 %0, {%1, %1};" : "=d"(r) : "f"(x));
    return r;
}

// d.lo += a.lo*b.lo ; d.hi += a.hi*b.hi   (one SASS FFMA2)
__device__ __forceinline__ void ffma2(double& d, double a, double b) {
    asm("fma.rn.f32x2 %0, %1, %2, %0;" : "+d"(d) : "l"(__double_as_longlong(a)), "l"(__double_as_longlong(b)));
}

__device__ __forceinline__ void unpack2(float& lo, float& hi, double p) {
    asm("mov.b64 {%0, %1}, %2;" : "=f"(lo), "=f"(hi) : "d"(p));
}

__global__ __launch_bounds__(256, 2)
void blur_kernel(const float* __restrict__ in,
                 const float* __restrict__ ker,
                 float* __restrict__ out)
{
    extern __shared__ float smem[];
    float*  tile = smem;                                   // IH x SW floats
    double* wp   = (double*)(smem + TILE_FLOATS);          // 22 x WPS pairs

    const int tid = threadIdx.x;
    const int bx = blockIdx.x;             // 0..5   W tiles
    const int by = blockIdx.y;             // 0..11  H tiles
    const int bz = blockIdx.z;             // 0..47  b*3+c
    const int b  = bz / CC;

    // ---- build weight-pair table: wp[t][j] = (w[t][j], w[t-1][j]), zero padded ----
    {
        const float* kb = ker + b * (KK * KK);
        float2* wpf = (float2*)wp;
        for (int idx = tid; idx < WP_PAIRS; idx += 256) {
            int t = idx / WPS;
            int j = idx - t * WPS;
            float lo = (j < KK && t <= KK - 1) ? kb[t * KK + j] : 0.f;       // w[t][j], w[21]=0
            float hi = (j < KK && t >= 1)      ? kb[(t - 1) * KK + j] : 0.f; // w[t-1][j], w[-1]=0
            wpf[idx] = make_float2(lo, hi);
        }
    }

    // ---- input halo tile, reflect indexing ----
    {
        const int gh0 = by * TH - PP;
        const int gw0 = bx * TW - PP;
        const float* img = in + (long)bz * (HH * WW);
        for (int idx = tid; idx < IH * SW; idx += 256) {
            int r  = idx / SW;
            int cc = idx - r * SW;
            int gh = reflect_idx(gh0 + r);
            int gw = reflect_idx(gw0 + cc);
            tile[idx] = img[gh * WW + gw];
        }
    }
    __syncthreads();

    const int tx = tid & 15;     // 0..15 -> 8-wide column group
    const int ty = tid >> 4;     // 0..15 -> 4-row group
    const int wc = tx * 8;       // local col of first output (32B aligned)
    const int rb = ty * 4;       // first output row of this thread

    // accumulators: lanes = (row q, row q+1)
    double pcA[8], pcB[8];
    #pragma unroll
    for (int c = 0; c < 8; ++c) { pcA[c] = 0.0; pcB[c] = 0.0; }

    double xb[28];   // broadcast pairs of the 28-float window

    #define LOADROW(r) do {                                                   \
        const float* rp_ = &tile[(rb + (r)) * SW + wc];                       \
        _Pragma("unroll")                                                     \
        for (int v = 0; v < 7; ++v) {                                         \
            float4 q_ = *reinterpret_cast<const float4*>(rp_ + 4 * v);        \
            xb[4*v+0] = bcast(q_.x); xb[4*v+1] = bcast(q_.y);                 \
            xb[4*v+2] = bcast(q_.z); xb[4*v+3] = bcast(q_.w);                 \
        }                                                                     \
    } while (0)

    // single accumulator: PC[c] += xb[j+c] * wrow[j]
    #define ACC1(PC, trow) do {                                               \
        const double* wr_ = &wp[(trow) * WPS];                                \
        _Pragma("unroll")                                                     \
        for (int j = 0; j < KK; ++j) {                                        \
            const double wv_ = wr_[j];                                        \
            _Pragma("unroll")                                                 \
            for (int c = 0; c < 8; ++c) ffma2(PC[c], xb[j + c], wv_);         \
        }                                                                     \
    } while (0)

    // both accumulators in one pass over the window
    #define ACC2(tA, tB) do {                                                 \
        const double* wa_ = &wp[(tA) * WPS];                                  \
        const double* wb_ = &wp[(tB) * WPS];                                  \
        _Pragma("unroll")                                                     \
        for (int j = 0; j < KK; ++j) {                                        \
            const double wvA_ = wa_[j];                                       \
            const double wvB_ = wb_[j];                                       \
            _Pragma("unroll")                                                 \
            for (int c = 0; c < 8; ++c) {                                     \
                ffma2(pcA[c], xb[j + c], wvA_);                               \
                ffma2(pcB[c], xb[j + c], wvB_);                               \
            }                                                                 \
        }                                                                     \
    } while (0)

    // r = 0, 1: only pcA (wp rows 0,1)
    LOADROW(0); ACC1(pcA, 0);
    LOADROW(1); ACC1(pcA, 1);

    // r = 2..21: pcA with wp[r], pcB with wp[r-2]
    #pragma unroll 1
    for (int r = 2; r <= 21; ++r) {
        LOADROW(r);
        ACC2(r, r - 2);
    }

    // r = 22, 23: only pcB (wp rows 20, 21)
    LOADROW(22); ACC1(pcB, 20);
    LOADROW(23); ACC1(pcB, 21);

    // ---- unpack lanes, write 4 x 8 outputs ----
    const int oh = by * TH + rb;
    const int ow = bx * TW + wc;
    float* op = out + (long)bz * (HH * WW) + (long)oh * WW + ow;

    float r0[8], r1[8], r2[8], r3[8];
    #pragma unroll
    for (int c = 0; c < 8; ++c) {
        unpack2(r0[c], r1[c], pcA[c]);
        unpack2(r2[c], r3[c], pcB[c]);
    }
    #pragma unroll
    for (int v = 0; v < 2; ++v) {
        *reinterpret_cast<float4*>(op + 0*WW + 4*v) = make_float4(r0[4*v], r0[4*v+1], r0[4*v+2], r0[4*v+3]);
        *reinterpret_cast<float4*>(op + 1*WW + 4*v) = make_float4(r1[4*v], r1[4*v+1], r1[4*v+2], r1[4*v+3]);
        *reinterpret_cast<float4*>(op + 2*WW + 4*v) = make_float4(r2[4*v], r2[4*v+1], r2[4*v+2], r2[4*v+3]);
        *reinterpret_cast<float4*>(op + 3*WW + 4*v) = make_float4(r3[4*v], r3[4*v+1], r3[4*v+2], r3[4*v+3]);
    }

    #undef LOADROW
    #undef ACC1
    #undef ACC2
}

extern "C" void kernel_launch(void* const* d_in, const int* in_sizes, int n_in,
                              void* d_out, int out_size)
{
    const float* in  = (const float*)d_in[0];   // (16,3,768,768)
    const float* ker = (const float*)d_in[1];   // (16,21,21)
    float* out = (float*)d_out;

    cudaFuncSetAttribute(blur_kernel,
                         cudaFuncAttributeMaxDynamicSharedMemorySize, SMEM_BYTES);

    dim3 grid(WW / TW, HH / TH, BB * CC);       // (6, 12, 48)
    blur_kernel<<<grid, 256, SMEM_BYTES>>>(in, ker, out);
}

// round 5
// speedup vs baseline: 2.5807x; 1.8142x over previous
#include <cuda_runtime.h>
#include <cuda_bf16.h>
#include <cstdint>

// Per-batch 21x21 cross-correlation, reflect padding 10.
// input: (16,3,768,768) f32   kernel: (16,21,21) f32   out: (16,3,768,768) f32
// FFMA2 (fma.rn.f32x2) with lanes = two adjacent OUTPUT ROWS.
// Weight pairs (w[i][j], w[i-1][j]) precomputed in a smem table (no per-use packing).

#define BB 16
#define CC 3
#define HH 768
#define WW 768
#define KK 21
#define PP 10

#define TH 64            // output rows per CTA (4 per thread: 16 ty groups)
#define TW 128           // output cols per CTA (8 per thread: 16 tx groups)
#define IH (TH + KK - 1) // 84 input rows in tile
#define SW 152           // smem tile row stride (floats), 16B aligned
#define WPS 24           // weight-pair table row stride (pairs)

#define TILE_FLOATS (IH * SW)          // 12768
#define WP_PAIRS    (22 * WPS)         // 528
#define SMEM_BYTES  (TILE_FLOATS * 4 + WP_PAIRS * 8)   // 51072 + 4224 = 55296

__device__ __forceinline__ int reflect_idx(int t) {
    if (t < 0) return -t;
    if (t >= HH) return 2 * HH - 2 - t;
    return t;
}

// broadcast float into both lanes of a 64b pair (held as double reg pair)
__device__ __forceinline__ double bcast(float x) {
    double r;
    asm("mov.b64 %0, {%1, %1};" : "=d"(r) : "f"(x));
    return r;
}

// d.lo += a.lo*b.lo ; d.hi += a.hi*b.hi   (one SASS FFMA2)
__device__ __forceinline__ void ffma2(double& d, double a, double b) {
    asm("fma.rn.f32x2 %0, %1, %2, %0;" : "+d"(d) : "l"(__double_as_longlong(a)), "l"(__double_as_longlong(b)));
}

__device__ __forceinline__ void unpack2(float& lo, float& hi, double p) {
    asm("mov.b64 {%0, %1}, %2;" : "=f"(lo), "=f"(hi) : "d"(p));
}

__global__ __launch_bounds__(256, 2)
void blur_kernel(const float* __restrict__ in,
                 const float* __restrict__ ker,
                 float* __restrict__ out)
{
    extern __shared__ float smem[];
    float*  tile = smem;                                   // IH x SW floats
    double* wp   = (double*)(smem + TILE_FLOATS);          // 22 x WPS pairs

    const int tid = threadIdx.x;
    const int bx = blockIdx.x;             // 0..5   W tiles
    const int by = blockIdx.y;             // 0..11  H tiles
    const int bz = blockIdx.z;             // 0..47  b*3+c
    const int b  = bz / CC;

    // ---- build weight-pair table: wp[t][j] = (w[t][j], w[t-1][j]), zero padded ----
    {
        const float* kb = ker + b * (KK * KK);
        float2* wpf = (float2*)wp;
        for (int idx = tid; idx < WP_PAIRS; idx += 256) {
            int t = idx / WPS;
            int j = idx - t * WPS;
            float lo = (j < KK && t <= KK - 1) ? kb[t * KK + j] : 0.f;       // w[t][j], w[21]=0
            float hi = (j < KK && t >= 1)      ? kb[(t - 1) * KK + j] : 0.f; // w[t-1][j], w[-1]=0
            wpf[idx] = make_float2(lo, hi);
        }
    }

    // ---- input halo tile, reflect indexing ----
    {
        const int gh0 = by * TH - PP;
        const int gw0 = bx * TW - PP;
        const float* img = in + (long)bz * (HH * WW);
        for (int idx = tid; idx < IH * SW; idx += 256) {
            int r  = idx / SW;
            int cc = idx - r * SW;
            int gh = reflect_idx(gh0 + r);
            int gw = reflect_idx(gw0 + cc);
            tile[idx] = img[gh * WW + gw];
        }
    }
    __syncthreads();

    const int tx = tid & 15;     // 0..15 -> 8-wide column group
    const int ty = tid >> 4;     // 0..15 -> 4-row group
    const int wc = tx * 8;       // local col of first output (32B aligned)
    const int rb = ty * 4;       // first output row of this thread

    // accumulators: lanes = (row q, row q+1)
    double pcA[8], pcB[8];
    #pragma unroll
    for (int c = 0; c < 8; ++c) { pcA[c] = 0.0; pcB[c] = 0.0; }

    double xb[28];   // broadcast pairs of the 28-float window

    #define LOADROW(r) do {                                                   \
        const float* rp_ = &tile[(rb + (r)) * SW + wc];                       \
        _Pragma("unroll")                                                     \
        for (int v = 0; v < 7; ++v) {                                         \
            float4 q_ = *reinterpret_cast<const float4*>(rp_ + 4 * v);        \
            xb[4*v+0] = bcast(q_.x); xb[4*v+1] = bcast(q_.y);                 \
            xb[4*v+2] = bcast(q_.z); xb[4*v+3] = bcast(q_.w);                 \
        }                                                                     \
    } while (0)

    // single accumulator: PC[c] += xb[j+c] * wrow[j]
    #define ACC1(PC, trow) do {                                               \
        const double* wr_ = &wp[(trow) * WPS];                                \
        _Pragma("unroll")                                                     \
        for (int j = 0; j < KK; ++j) {                                        \
            const double wv_ = wr_[j];                                        \
            _Pragma("unroll")                                                 \
            for (int c = 0; c < 8; ++c) ffma2(PC[c], xb[j + c], wv_);         \
        }                                                                     \
    } while (0)

    // both accumulators in one pass over the window
    #define ACC2(tA, tB) do {                                                 \
        const double* wa_ = &wp[(tA) * WPS];                                  \
        const double* wb_ = &wp[(tB) * WPS];                                  \
        _Pragma("unroll")                                                     \
        for (int j = 0; j < KK; ++j) {                                        \
            const double wvA_ = wa_[j];                                       \
            const double wvB_ = wb_[j];                                       \
            _Pragma("unroll")                                                 \
            for (int c = 0; c < 8; ++c) {                                     \
                ffma2(pcA[c], xb[j + c], wvA_);                               \
                ffma2(pcB[c], xb[j + c], wvB_);                               \
            }                                                                 \
        }                                                                     \
    } while (0)

    // r = 0, 1: only pcA (wp rows 0,1)
    LOADROW(0); ACC1(pcA, 0);
    LOADROW(1); ACC1(pcA, 1);

    // r = 2..21: pcA with wp[r], pcB with wp[r-2]
    #pragma unroll 1
    for (int r = 2; r <= 21; ++r) {
        LOADROW(r);
        ACC2(r, r - 2);
    }

    // r = 22, 23: only pcB (wp rows 20, 21)
    LOADROW(22); ACC1(pcB, 20);
    LOADROW(23); ACC1(pcB, 21);

    // ---- unpack lanes, write 4 x 8 outputs ----
    const int oh = by * TH + rb;
    const int ow = bx * TW + wc;
    float* op = out + (long)bz * (HH * WW) + (long)oh * WW + ow;

    float r0[8], r1[8], r2[8], r3[8];
    #pragma unroll
    for (int c = 0; c < 8; ++c) {
        unpack2(r0[c], r1[c], pcA[c]);
        unpack2(r2[c], r3[c], pcB[c]);
    }
    #pragma unroll
    for (int v = 0; v < 2; ++v) {
        *reinterpret_cast<float4*>(op + 0*WW + 4*v) = make_float4(r0[4*v], r0[4*v+1], r0[4*v+2], r0[4*v+3]);
        *reinterpret_cast<float4*>(op + 1*WW + 4*v) = make_float4(r1[4*v], r1[4*v+1], r1[4*v+2], r1[4*v+3]);
        *reinterpret_cast<float4*>(op + 2*WW + 4*v) = make_float4(r2[4*v], r2[4*v+1], r2[4*v+2], r2[4*v+3]);
        *reinterpret_cast<float4*>(op + 3*WW + 4*v) = make_float4(r3[4*v], r3[4*v+1], r3[4*v+2], r3[4*v+3]);
    }

    #undef LOADROW
    #undef ACC1
    #undef ACC2
}

extern "C" void kernel_launch(void* const* d_in, const int* in_sizes, int n_in,
                              void* d_out, int out_size)
{
    const float* in  = (const float*)d_in[0];   // (16,3,768,768)
    const float* ker = (const float*)d_in[1];   // (16,21,21)
    float* out = (float*)d_out;

    cudaFuncSetAttribute(blur_kernel,
                         cudaFuncAttributeMaxDynamicSharedMemorySize, SMEM_BYTES);

    dim3 grid(WW / TW, HH / TH, BB * CC);       // (6, 12, 48)
    blur_kernel<<<grid, 256, SMEM_BYTES>>>(in, ker, out);
}

// round 6
// speedup vs baseline: 2.7134x; 1.0514x over previous
#include <cuda_runtime.h>
#include <cuda_bf16.h>
#include <cstdint>

// Per-batch 21x21 cross-correlation, reflect padding 10.
// input: (16,3,768,768) f32   kernel: (16,21,21) f32   out: (16,3,768,768) f32
// FFMA2 (fma.rn.f32x2), lanes = two adjacent OUTPUT ROWS; weight pairs in smem table.
// R6: 3 CTAs/SM (launch_bounds 256,3) + division-free warp-structured halo load.

#define BB 16
#define CC 3
#define HH 768
#define WW 768
#define KK 21
#define PP 10

#define TH 64            // output rows per CTA (4 per thread: 16 ty groups)
#define TW 128           // output cols per CTA (8 per thread: 16 tx groups)
#define IH (TH + KK - 1) // 84 input rows in tile
#define IW (TW + KK - 1) // 148 input cols actually needed
#define SW 152           // smem tile row stride (floats), 16B aligned
#define WPS 24           // weight-pair table row stride (pairs)

#define TILE_FLOATS (IH * SW)          // 12768
#define WP_PAIRS    (22 * WPS)         // 528
#define SMEM_BYTES  (TILE_FLOATS * 4 + WP_PAIRS * 8)   // 55296

__device__ __forceinline__ int reflect_idx(int t) {
    if (t < 0) return -t;
    if (t >= HH) return 2 * HH - 2 - t;
    return t;
}

// broadcast float into both lanes of a 64b pair (held as double reg pair)
__device__ __forceinline__ double bcast(float x) {
    double r;
    asm("mov.b64 %0, {%1, %1};" : "=d"(r) : "f"(x));
    return r;
}

// d.lo += a.lo*b.lo ; d.hi += a.hi*b.hi   (one SASS FFMA2)
__device__ __forceinline__ void ffma2(double& d, double a, double b) {
    asm("fma.rn.f32x2 %0, %1, %2, %0;" : "+d"(d) : "l"(__double_as_longlong(a)), "l"(__double_as_longlong(b)));
}

__device__ __forceinline__ void unpack2(float& lo, float& hi, double p) {
    asm("mov.b64 {%0, %1}, %2;" : "=f"(lo), "=f"(hi) : "d"(p));
}

__global__ __launch_bounds__(256, 3)
void blur_kernel(const float* __restrict__ in,
                 const float* __restrict__ ker,
                 float* __restrict__ out)
{
    extern __shared__ float smem[];
    float*  tile = smem;                                   // IH x SW floats
    double* wp   = (double*)(smem + TILE_FLOATS);          // 22 x WPS pairs

    const int tid  = threadIdx.x;
    const int lane = tid & 31;
    const int wrp  = tid >> 5;             // 0..7
    const int bx = blockIdx.x;             // 0..5   W tiles
    const int by = blockIdx.y;             // 0..11  H tiles
    const int bz = blockIdx.z;             // 0..47  b*3+c
    const int b  = bz / CC;

    // ---- build weight-pair table: wp[t][j] = (w[t][j], w[t-1][j]), zero padded ----
    // 22 rows; warp w handles rows w, w+8, w+16. Lane j < WPS columns (21 real + 3 pad).
    {
        const float* kb = ker + b * (KK * KK);
        float2* wpf = (float2*)wp;
        for (int t = wrp; t < 22; t += 8) {
            int j = lane;
            if (j < WPS) {
                float lo = (j < KK && t <= KK - 1) ? kb[t * KK + j] : 0.f;
                float hi = (j < KK && t >= 1)      ? kb[(t - 1) * KK + j] : 0.f;
                wpf[t * WPS + j] = make_float2(lo, hi);
            }
        }
    }

    // ---- input halo tile: warp-per-row, lane-per-col, no divisions ----
    {
        const int gh0 = by * TH - PP;
        const int gw0 = bx * TW - PP;
        const float* img = in + (long)bz * (HH * WW);
        #pragma unroll 1
        for (int r = wrp; r < IH; r += 8) {
            const float* src = img + (long)reflect_idx(gh0 + r) * WW;
            float* dst = &tile[r * SW];
            #pragma unroll
            for (int c5 = 0; c5 < 5; ++c5) {
                int cc = c5 * 32 + lane;             // 0..159
                if (cc < IW) {
                    dst[cc] = src[reflect_idx(gw0 + cc)];
                }
            }
        }
    }
    __syncthreads();

    const int tx = tid & 15;     // 0..15 -> 8-wide column group
    const int ty = tid >> 4;     // 0..15 -> 4-row group
    const int wc = tx * 8;       // local col of first output (32B aligned)
    const int rb = ty * 4;       // first output row of this thread

    // accumulators: lanes = (row q, row q+1)
    double pcA[8], pcB[8];
    #pragma unroll
    for (int c = 0; c < 8; ++c) { pcA[c] = 0.0; pcB[c] = 0.0; }

    double xb[28];   // broadcast pairs of the 28-float window

    #define LOADROW(r) do {                                                   \
        const float* rp_ = &tile[(rb + (r)) * SW + wc];                       \
        _Pragma("unroll")                                                     \
        for (int v = 0; v < 7; ++v) {                                         \
            float4 q_ = *reinterpret_cast<const float4*>(rp_ + 4 * v);        \
            xb[4*v+0] = bcast(q_.x); xb[4*v+1] = bcast(q_.y);                 \
            xb[4*v+2] = bcast(q_.z); xb[4*v+3] = bcast(q_.w);                 \
        }                                                                     \
    } while (0)

    // single accumulator: PC[c] += xb[j+c] * wrow[j]
    #define ACC1(PC, trow) do {                                               \
        const double* wr_ = &wp[(trow) * WPS];                                \
        _Pragma("unroll")                                                     \
        for (int j = 0; j < KK; ++j) {                                        \
            const double wv_ = wr_[j];                                        \
            _Pragma("unroll")                                                 \
            for (int c = 0; c < 8; ++c) ffma2(PC[c], xb[j + c], wv_);         \
        }                                                                     \
    } while (0)

    // both accumulators in one pass over the window
    #define ACC2(tA, tB) do {                                                 \
        const double* wa_ = &wp[(tA) * WPS];                                  \
        const double* wb_ = &wp[(tB) * WPS];                                  \
        _Pragma("unroll")                                                     \
        for (int j = 0; j < KK; ++j) {                                        \
            const double wvA_ = wa_[j];                                       \
            const double wvB_ = wb_[j];                                       \
            _Pragma("unroll")                                                 \
            for (int c = 0; c < 8; ++c) {                                     \
                ffma2(pcA[c], xb[j + c], wvA_);                               \
                ffma2(pcB[c], xb[j + c], wvB_);                               \
            }                                                                 \
        }                                                                     \
    } while (0)

    // r = 0, 1: only pcA (wp rows 0,1)
    LOADROW(0); ACC1(pcA, 0);
    LOADROW(1); ACC1(pcA, 1);

    // r = 2..21: pcA with wp[r], pcB with wp[r-2]
    #pragma unroll 1
    for (int r = 2; r <= 21; ++r) {
        LOADROW(r);
        ACC2(r, r - 2);
    }

    // r = 22, 23: only pcB (wp rows 20, 21)
    LOADROW(22); ACC1(pcB, 20);
    LOADROW(23); ACC1(pcB, 21);

    // ---- unpack lanes, write 4 x 8 outputs ----
    const int oh = by * TH + rb;
    const int ow = bx * TW + wc;
    float* op = out + (long)bz * (HH * WW) + (long)oh * WW + ow;

    float r0[8], r1[8], r2[8], r3[8];
    #pragma unroll
    for (int c = 0; c < 8; ++c) {
        unpack2(r0[c], r1[c], pcA[c]);
        unpack2(r2[c], r3[c], pcB[c]);
    }
    #pragma unroll
    for (int v = 0; v < 2; ++v) {
        *reinterpret_cast<float4*>(op + 0*WW + 4*v) = make_float4(r0[4*v], r0[4*v+1], r0[4*v+2], r0[4*v+3]);
        *reinterpret_cast<float4*>(op + 1*WW + 4*v) = make_float4(r1[4*v], r1[4*v+1], r1[4*v+2], r1[4*v+3]);
        *reinterpret_cast<float4*>(op + 2*WW + 4*v) = make_float4(r2[4*v], r2[4*v+1], r2[4*v+2], r2[4*v+3]);
        *reinterpret_cast<float4*>(op + 3*WW + 4*v) = make_float4(r3[4*v], r3[4*v+1], r3[4*v+2], r3[4*v+3]);
    }

    #undef LOADROW
    #undef ACC1
    #undef ACC2
}

extern "C" void kernel_launch(void* const* d_in, const int* in_sizes, int n_in,
                              void* d_out, int out_size)
{
    const float* in  = (const float*)d_in[0];   // (16,3,768,768)
    const float* ker = (const float*)d_in[1];   // (16,21,21)
    float* out = (float*)d_out;

    cudaFuncSetAttribute(blur_kernel,
                         cudaFuncAttributeMaxDynamicSharedMemorySize, SMEM_BYTES);

    dim3 grid(WW / TW, HH / TH, BB * CC);       // (6, 12, 48)
    blur_kernel<<<grid, 256, SMEM_BYTES>>>(in, ker, out);
}

// round 7
// speedup vs baseline: 2.8803x; 1.0615x over previous
#include <cuda_runtime.h>
#include <cuda_bf16.h>
#include <cstdint>

// Per-batch 21x21 cross-correlation, reflect padding 10.
// input: (16,3,768,768) f32   kernel: (16,21,21) f32   out: (16,3,768,768) f32
// FFMA2 (fma.rn.f32x2), lanes = two adjacent OUTPUT ROWS.
// R7: cp.async halo load (no LDG->STS chain) + weight QUAD table (one LDS.128
//     feeds both accumulator sets per j).

#define BB 16
#define CC 3
#define HH 768
#define WW 768
#define KK 21
#define PP 10

#define TH 64            // output rows per CTA (4 per thread: 16 ty groups)
#define TW 128           // output cols per CTA (8 per thread: 16 tx groups)
#define IH (TH + KK - 1) // 84 input rows in tile
#define IW (TW + KK - 1) // 148 input cols needed
#define SW 152           // smem tile row stride (floats), 16B aligned
#define QJ 24            // quads per table row (21 real + pad)

#define TILE_FLOATS (IH * SW)                 // 12768
#define QUAD_COUNT  (24 * QJ)                 // 576 quads (16B each)
#define SMEM_BYTES  (TILE_FLOATS * 4 + QUAD_COUNT * 16)   // 51072 + 9216 = 60288

__device__ __forceinline__ int reflect_idx(int t) {
    if (t < 0) return -t;
    if (t >= HH) return 2 * HH - 2 - t;
    return t;
}

// broadcast float into both lanes of a 64b pair
__device__ __forceinline__ double bcast(float x) {
    double r;
    asm("mov.b64 %0, {%1, %1};" : "=d"(r) : "f"(x));
    return r;
}

// d.lo += a.lo*b.lo ; d.hi += a.hi*b.hi   (one SASS FFMA2)
__device__ __forceinline__ void ffma2(double& d, double a, double b) {
    asm("fma.rn.f32x2 %0, %1, %2, %0;"
        : "+d"(d) : "l"(__double_as_longlong(a)), "l"(__double_as_longlong(b)));
}

__device__ __forceinline__ void unpack2(float& lo, float& hi, double p) {
    asm("mov.b64 {%0, %1}, %2;" : "=f"(lo), "=f"(hi) : "d"(p));
}

__device__ __forceinline__ void cp_async4(uint32_t dst_smem, const float* src) {
    asm volatile("cp.async.ca.shared.global [%0], [%1], 4;"
                 :: "r"(dst_smem), "l"(src));
}

__global__ __launch_bounds__(256, 3)
void blur_kernel(const float* __restrict__ in,
                 const float* __restrict__ ker,
                 float* __restrict__ out)
{
    extern __shared__ float smem[];
    float* tile = smem;                                    // IH x SW floats
    float* qtab = smem + TILE_FLOATS;                      // 24 x QJ quads (float4)

    const int tid  = threadIdx.x;
    const int lane = tid & 31;
    const int wrp  = tid >> 5;             // 0..7
    const int bx = blockIdx.x;             // 0..5   W tiles
    const int by = blockIdx.y;             // 0..11  H tiles
    const int bz = blockIdx.z;             // 0..47  b*3+c
    const int b  = bz / CC;

    const uint32_t tile_base = (uint32_t)__cvta_generic_to_shared(tile);
    const uint32_t kern_base = (uint32_t)__cvta_generic_to_shared(qtab);

    // ---- input halo tile via cp.async: warp-per-row, lane-per-col ----
    {
        const int gh0 = by * TH - PP;
        const int gw0 = bx * TW - PP;
        const float* img = in + (long)bz * (HH * WW);
        #pragma unroll 1
        for (int r = wrp; r < IH; r += 8) {
            const float* src = img + (long)reflect_idx(gh0 + r) * WW;
            uint32_t dst = tile_base + (uint32_t)(r * SW * 4);
            #pragma unroll
            for (int c5 = 0; c5 < 5; ++c5) {
                int cc = c5 * 32 + lane;             // 0..159
                if (cc < IW) {
                    cp_async4(dst + cc * 4, src + reflect_idx(gw0 + cc));
                }
            }
        }
    }

    // ---- build weight QUAD table while cp.async is in flight ----
    // quad[t][j] = (w[t][j], w[t-1][j], w[t-2][j], w[t-3][j]), zeros outside [0,20]
    {
        const float* kb = ker + b * (KK * KK);
        float4* q4 = (float4*)qtab;
        #pragma unroll 1
        for (int idx = tid; idx < QUAD_COUNT; idx += 256) {
            int t = idx / QJ;
            int j = idx - t * QJ;
            float v0 = 0.f, v1 = 0.f, v2 = 0.f, v3 = 0.f;
            if (j < KK) {
                if (t     <= 20)           v0 = kb[t * KK + j];
                if (t >= 1 && t - 1 <= 20) v1 = kb[(t - 1) * KK + j];
                if (t >= 2 && t - 2 <= 20) v2 = kb[(t - 2) * KK + j];
                if (t >= 3 && t - 3 <= 20) v3 = kb[(t - 3) * KK + j];
            }
            q4[idx] = make_float4(v0, v1, v2, v3);
        }
    }

    asm volatile("cp.async.commit_group;" ::: "memory");
    asm volatile("cp.async.wait_group 0;" ::: "memory");
    __syncthreads();

    const int tx = tid & 15;     // 0..15 -> 8-wide column group
    const int ty = tid >> 4;     // 0..15 -> 4-row group
    const int wc = tx * 8;       // local col of first output
    const int rb = ty * 4;       // first output row of this thread

    // accumulators: pcA lanes = (row rb, rb+1), pcB lanes = (row rb+2, rb+3)
    double pcA[8], pcB[8];
    #pragma unroll
    for (int c = 0; c < 8; ++c) { pcA[c] = 0.0; pcB[c] = 0.0; }

    double xb[28];   // broadcast pairs of the 28-float window

    #define LOADROW(r) do {                                                   \
        const float* rp_ = &tile[(rb + (r)) * SW + wc];                       \
        _Pragma("unroll")                                                     \
        for (int v = 0; v < 7; ++v) {                                         \
            float4 q_ = *reinterpret_cast<const float4*>(rp_ + 4 * v);        \
            xb[4*v+0] = bcast(q_.x); xb[4*v+1] = bcast(q_.y);                 \
            xb[4*v+2] = bcast(q_.z); xb[4*v+3] = bcast(q_.w);                 \
        }                                                                     \
    } while (0)

    // both acc sets, one LDS.128 per j: lo pair -> pcA, hi pair -> pcB
    #define ACC2Q(r) do {                                                     \
        const uint32_t qa_ = kern_base + (uint32_t)((r) * (QJ * 16));         \
        _Pragma("unroll")                                                     \
        for (int j = 0; j < KK; ++j) {                                        \
            unsigned long long la_, lb_;                                      \
            asm volatile("ld.shared.v2.u64 {%0, %1}, [%2];"                   \
                         : "=l"(la_), "=l"(lb_) : "r"(qa_ + j * 16));         \
            const double wA_ = __longlong_as_double(la_);                     \
            const double wB_ = __longlong_as_double(lb_);                     \
            _Pragma("unroll")                                                 \
            for (int c = 0; c < 8; ++c) {                                     \
                ffma2(pcA[c], xb[j + c], wA_);                                \
                ffma2(pcB[c], xb[j + c], wB_);                                \
            }                                                                 \
        }                                                                     \
    } while (0)

    // single acc set; off = 0 -> lo pair (pcA), off = 8 -> hi pair (pcB)
    #define ACC1P(PC, r, off) do {                                            \
        const uint32_t qa_ = kern_base + (uint32_t)((r) * (QJ * 16) + (off)); \
        _Pragma("unroll")                                                     \
        for (int j = 0; j < KK; ++j) {                                        \
            unsigned long long l_;                                            \
            asm volatile("ld.shared.b64 %0, [%1];"                            \
                         : "=l"(l_) : "r"(qa_ + j * 16));                     \
            const double w_ = __longlong_as_double(l_);                       \
            _Pragma("unroll")                                                 \
            for (int c = 0; c < 8; ++c) ffma2(PC[c], xb[j + c], w_);          \
        }                                                                     \
    } while (0)

    // r = 0,1: only pcA (pairs (w0,0), (w1,w0))
    LOADROW(0); ACC1P(pcA, 0, 0);
    LOADROW(1); ACC1P(pcA, 1, 0);

    // r = 2..21: pcA with (w[r],w[r-1]), pcB with (w[r-2],w[r-3])
    #pragma unroll 1
    for (int r = 2; r <= 21; ++r) {
        LOADROW(r);
        ACC2Q(r);
    }

    // r = 22,23: only pcB (pairs (w20,w19), (w21=0->w20? no: (w20,w19) at r=22 hi, (0+w21? ) )
    LOADROW(22); ACC1P(pcB, 22, 8);   // hi pair of quad[22] = (w20, w19)... = (w[22-2], w[22-3]) ✓
    LOADROW(23); ACC1P(pcB, 23, 8);   // hi pair of quad[23] = (w21=0? no: w[21]=0, w[20]) ✓

    // ---- unpack lanes, write 4 x 8 outputs ----
    const int oh = by * TH + rb;
    const int ow = bx * TW + wc;
    float* op = out + (long)bz * (HH * WW) + (long)oh * WW + ow;

    float r0[8], r1[8], r2[8], r3[8];
    #pragma unroll
    for (int c = 0; c < 8; ++c) {
        unpack2(r0[c], r1[c], pcA[c]);
        unpack2(r2[c], r3[c], pcB[c]);
    }
    #pragma unroll
    for (int v = 0; v < 2; ++v) {
        *reinterpret_cast<float4*>(op + 0*WW + 4*v) = make_float4(r0[4*v], r0[4*v+1], r0[4*v+2], r0[4*v+3]);
        *reinterpret_cast<float4*>(op + 1*WW + 4*v) = make_float4(r1[4*v], r1[4*v+1], r1[4*v+2], r1[4*v+3]);
        *reinterpret_cast<float4*>(op + 2*WW + 4*v) = make_float4(r2[4*v], r2[4*v+1], r2[4*v+2], r2[4*v+3]);
        *reinterpret_cast<float4*>(op + 3*WW + 4*v) = make_float4(r3[4*v], r3[4*v+1], r3[4*v+2], r3[4*v+3]);
    }

    #undef LOADROW
    #undef ACC2Q
    #undef ACC1P
}

extern "C" void kernel_launch(void* const* d_in, const int* in_sizes, int n_in,
                              void* d_out, int out_size)
{
    const float* in  = (const float*)d_in[0];   // (16,3,768,768)
    const float* ker = (const float*)d_in[1];   // (16,21,21)
    float* out = (float*)d_out;

    cudaFuncSetAttribute(blur_kernel,
                         cudaFuncAttributeMaxDynamicSharedMemorySize, SMEM_BYTES);

    dim3 grid(WW / TW, HH / TH, BB * CC);       // (6, 12, 48)
    blur_kernel<<<grid, 256, SMEM_BYTES>>>(in, ker, out);
}